// round 2
// baseline (speedup 1.0000x reference)
#include <cuda_runtime.h>
#include <mma.h>
#include <math.h>

using namespace nvcuda;

// Problem constants
#define TT    256
#define BSZ   64
#define DIN   1024
#define HIDN  1024
#define NL    2
#define H4    (4 * HIDN)
#define MTOT  (TT * BSZ)          // 16384
#define BH    (BSZ * HIDN)        // 65536

// ---------------- device scratch (no allocations allowed) ----------------
__device__ float g_Xp[(size_t)MTOT * H4];   // precomputed x@Wx^T + b for current layer (256 MB)
__device__ float g_H0[(size_t)MTOT * HIDN]; // layer-0 hidden outputs for all t (64 MB)
__device__ float g_c[NL][BH];               // cell states
__device__ float g_zero[BH];                // all-zero h for t=0

// ---------------- init: zero cell states ----------------
__global__ void init_kernel() {
    int i = blockIdx.x * blockDim.x + threadIdx.x;
    if (i < BH) {
        g_c[0][i] = 0.f;
        g_c[1][i] = 0.f;
        g_zero[i] = 0.f;
    }
}

// ---------------- precompute GEMM: C = A[M,K] @ W[N,K]^T + bias[N] -> g_Xp ----------------
// tf32 wmma, 64x64 block tile, K-tile 32, 256 threads (8 warps: 4 m-tiles x 2 n-tiles)
__global__ void gemm_xp_kernel(const float* __restrict__ A,
                               const float* __restrict__ W,
                               const float* __restrict__ bias,
                               int M, int N, int K) {
    __shared__ float As[64][36];
    __shared__ float Ws[64][36];
    __shared__ float Cs[64][68];

    const int tid  = threadIdx.x;
    const int warp = tid >> 5;
    const int wm   = warp & 3;    // 0..3 -> 16-row slice
    const int wn   = warp >> 2;   // 0..1 -> 32-col slice
    const int row0A = blockIdx.y * 64;
    const int row0W = blockIdx.x * 64;

    wmma::fragment<wmma::accumulator, 16, 16, 8, float> acc[2];
    wmma::fill_fragment(acc[0], 0.f);
    wmma::fill_fragment(acc[1], 0.f);

    for (int k0 = 0; k0 < K; k0 += 32) {
#pragma unroll
        for (int r = 0; r < 2; r++) {
            int row = r * 32 + (tid >> 3);
            int c4  = (tid & 7) * 4;
            *(float4*)&As[row][c4] =
                *(const float4*)(A + (size_t)(row0A + row) * K + k0 + c4);
            *(float4*)&Ws[row][c4] =
                *(const float4*)(W + (size_t)(row0W + row) * K + k0 + c4);
        }
        __syncthreads();
#pragma unroll
        for (int kk = 0; kk < 32; kk += 8) {
            wmma::fragment<wmma::matrix_a, 16, 16, 8, wmma::precision::tf32, wmma::row_major> af;
            wmma::load_matrix_sync(af, &As[wm * 16][kk], 36);
#pragma unroll
            for (int i = 0; i < af.num_elements; i++) af.x[i] = wmma::__float_to_tf32(af.x[i]);
#pragma unroll
            for (int j = 0; j < 2; j++) {
                wmma::fragment<wmma::matrix_b, 16, 16, 8, wmma::precision::tf32, wmma::col_major> bf;
                wmma::load_matrix_sync(bf, &Ws[wn * 32 + j * 16][kk], 36);
#pragma unroll
                for (int i = 0; i < bf.num_elements; i++) bf.x[i] = wmma::__float_to_tf32(bf.x[i]);
                wmma::mma_sync(acc[j], af, bf, acc[j]);
            }
        }
        __syncthreads();
    }

    wmma::store_matrix_sync(&Cs[wm * 16][wn * 32],      acc[0], 68, wmma::mem_row_major);
    wmma::store_matrix_sync(&Cs[wm * 16][wn * 32 + 16], acc[1], 68, wmma::mem_row_major);
    __syncthreads();

    for (int idx = tid; idx < 64 * 64; idx += 256) {
        int r = idx >> 6, c = idx & 63;
        g_Xp[(size_t)(row0A + r) * N + row0W + c] = Cs[r][c] + bias[row0W + c];
    }
}

// ---------------- fused recurrent step ----------------
// One kernel per (layer, t). Grid = 64 CTAs, each owns 16 hidden units across
// all 4 gates (64 Wh rows) and all 64 batch rows. GEMM partial h@Wh^T (tf32 wmma)
// then LSTM cell epilogue in the same kernel.
__global__ void lstm_step_kernel(const float* __restrict__ Hprev, // [BSZ, HIDN]
                                 const float* __restrict__ Wh,    // [H4, HIDN]
                                 const float* __restrict__ Xp,    // [BSZ, H4] (row t)
                                 float* __restrict__ Hout,        // [BSZ, HIDN]
                                 int layer) {
    __shared__ float As[64][36];
    __shared__ float Ws[64][36];
    __shared__ float Gs[64][68];

    const int tid  = threadIdx.x;
    const int warp = tid >> 5;
    const int gate = warp >> 1;   // 0..3
    const int wm   = warp & 1;    // 0..1 -> 32 batch rows
    const int j0   = blockIdx.x * 16;

    wmma::fragment<wmma::accumulator, 16, 16, 8, float> acc[2];
    wmma::fill_fragment(acc[0], 0.f);
    wmma::fill_fragment(acc[1], 0.f);

    for (int k0 = 0; k0 < HIDN; k0 += 32) {
#pragma unroll
        for (int r = 0; r < 2; r++) {
            int row = r * 32 + (tid >> 3);
            int c4  = (tid & 7) * 4;
            *(float4*)&As[row][c4] =
                *(const float4*)(Hprev + (size_t)row * HIDN + k0 + c4);
            int g_ = row >> 4;            // gate of this smem row
            int u  = row & 15;            // unit within CTA slice
            int wr = g_ * HIDN + j0 + u;  // Wh global row
            *(float4*)&Ws[row][c4] =
                *(const float4*)(Wh + (size_t)wr * HIDN + k0 + c4);
        }
        __syncthreads();
#pragma unroll
        for (int kk = 0; kk < 32; kk += 8) {
            wmma::fragment<wmma::matrix_b, 16, 16, 8, wmma::precision::tf32, wmma::col_major> bf;
            wmma::load_matrix_sync(bf, &Ws[gate * 16][kk], 36);
#pragma unroll
            for (int i = 0; i < bf.num_elements; i++) bf.x[i] = wmma::__float_to_tf32(bf.x[i]);
#pragma unroll
            for (int f = 0; f < 2; f++) {
                wmma::fragment<wmma::matrix_a, 16, 16, 8, wmma::precision::tf32, wmma::row_major> af;
                wmma::load_matrix_sync(af, &As[wm * 32 + f * 16][kk], 36);
#pragma unroll
                for (int i = 0; i < af.num_elements; i++) af.x[i] = wmma::__float_to_tf32(af.x[i]);
                wmma::mma_sync(acc[f], af, bf, acc[f]);
            }
        }
        __syncthreads();
    }

    wmma::store_matrix_sync(&Gs[wm * 32][gate * 16],      acc[0], 68, wmma::mem_row_major);
    wmma::store_matrix_sync(&Gs[wm * 32 + 16][gate * 16], acc[1], 68, wmma::mem_row_major);
    __syncthreads();

    // LSTM cell epilogue: 64 batch x 16 units = 1024 elements, 4 per thread
    for (int idx = tid; idx < 64 * 16; idx += 256) {
        int b_ = idx >> 4;
        int u  = idx & 15;
        int j  = j0 + u;
        const float* xb = Xp + (size_t)b_ * H4;
        float gi = Gs[b_][u]           + xb[j];
        float gf = Gs[b_][16 + u]      + xb[HIDN + j];
        float go = Gs[b_][32 + u]      + xb[2 * HIDN + j];
        float gc = Gs[b_][48 + u]      + xb[3 * HIDN + j];
        float si = 1.f / (1.f + expf(-gi));
        float sf = 1.f / (1.f + expf(-gf));
        float so = 1.f / (1.f + expf(-go));
        float cold = g_c[layer][b_ * HIDN + j];
        float cn = sf * cold + si * tanhf(gc);
        float h  = so * tanhf(cn);
        g_c[layer][b_ * HIDN + j] = cn;
        Hout[(size_t)b_ * HIDN + j] = h;
    }
}

// ---------------- finalize: Hf / Cf ----------------
__global__ void finalize_kernel(const float* __restrict__ h0_last,
                                const float* __restrict__ h1_last,
                                float* __restrict__ Hf,
                                float* __restrict__ Cf) {
    int i = blockIdx.x * blockDim.x + threadIdx.x;
    if (i < BH) {
        Hf[i]      = h0_last[i];
        Hf[BH + i] = h1_last[i];
        Cf[i]      = g_c[0][i];
        Cf[BH + i] = g_c[1][i];
    }
}

// ---------------- launch ----------------
extern "C" void kernel_launch(void* const* d_in, const int* in_sizes, int n_in,
                              void* d_out, int out_size) {
    const float* X    = (const float*)d_in[0]; // [T, B, D]
    const float* Wx   = (const float*)d_in[1]; // [L, 4H, D]
    const float* Wh   = (const float*)d_in[2]; // [L, 4H, H]
    const float* bias = (const float*)d_in[3]; // [L, 4H]

    float* out     = (float*)d_out;
    float* outputs = out;                       // [T, B, H]
    float* Hf      = out + (size_t)TT * BH / 1; // after outputs
    Hf = out + (size_t)TT * BSZ * HIDN;
    float* Cf      = Hf + (size_t)NL * BH;

    float *Xp_p = nullptr, *H0_p = nullptr, *zero_p = nullptr;
    cudaGetSymbolAddress((void**)&Xp_p, g_Xp);
    cudaGetSymbolAddress((void**)&H0_p, g_H0);
    cudaGetSymbolAddress((void**)&zero_p, g_zero);

    init_kernel<<<(BH + 255) / 256, 256>>>();

    dim3 gg(H4 / 64, MTOT / 64);

    // Layer 0: precompute X @ Wx0^T + b0
    gemm_xp_kernel<<<gg, 256>>>(X, Wx, bias, MTOT, H4, DIN);
    // Layer 0 recurrence
    for (int t = 0; t < TT; t++) {
        const float* hp = t ? (H0_p + (size_t)(t - 1) * BH / 1) : zero_p;
        hp = t ? (H0_p + (size_t)(t - 1) * BSZ * HIDN) : zero_p;
        lstm_step_kernel<<<64, 256>>>(hp, Wh,
                                      Xp_p + (size_t)t * BSZ * H4,
                                      H0_p + (size_t)t * BSZ * HIDN, 0);
    }

    // Layer 1: precompute H0 @ Wx1^T + b1
    gemm_xp_kernel<<<gg, 256>>>(H0_p, Wx + (size_t)H4 * DIN, bias + H4, MTOT, H4, HIDN);
    // Layer 1 recurrence (writes directly to outputs region of d_out)
    for (int t = 0; t < TT; t++) {
        const float* hp = t ? (outputs + (size_t)(t - 1) * BSZ * HIDN) : zero_p;
        lstm_step_kernel<<<64, 256>>>(hp, Wh + (size_t)H4 * HIDN,
                                      Xp_p + (size_t)t * BSZ * H4,
                                      outputs + (size_t)t * BSZ * HIDN, 1);
    }

    finalize_kernel<<<(BH + 255) / 256, 256>>>(
        H0_p + (size_t)(TT - 1) * BSZ * HIDN,
        outputs + (size_t)(TT - 1) * BSZ * HIDN,
        Hf, Cf);
}

// round 3
// speedup vs baseline: 1.0055x; 1.0055x over previous
#include <cuda_runtime.h>
#include <mma.h>
#include <math.h>

using namespace nvcuda;

// Problem constants
#define TT    256
#define BSZ   64
#define DIN   1024
#define HIDN  1024
#define NL    2
#define H4    (4 * HIDN)
#define MTOT  (TT * BSZ)          // 16384
#define BH    (BSZ * HIDN)        // 65536

// ---------------- device scratch (no allocations allowed) ----------------
__device__ float g_Xp[(size_t)MTOT * H4];   // precomputed x@Wx^T + b for current layer (256 MB)
__device__ float g_H0[(size_t)MTOT * HIDN]; // layer-0 hidden outputs for all t (64 MB)
__device__ float g_c[NL][BH];               // cell states
__device__ float g_zero[BH];                // all-zero h for t=0

// ---------------- init: zero cell states ----------------
__global__ void init_kernel() {
    int i = blockIdx.x * blockDim.x + threadIdx.x;
    if (i < BH) {
        g_c[0][i] = 0.f;
        g_c[1][i] = 0.f;
        g_zero[i] = 0.f;
    }
}

// ---------------- precompute GEMM: C = A[M,K] @ W[N,K]^T + bias[N] -> g_Xp ----------------
// tf32 wmma, 64x64 block tile, K-tile 32, 256 threads (8 warps: 4 m-tiles x 2 n-tiles)
__global__ void gemm_xp_kernel(const float* __restrict__ A,
                               const float* __restrict__ W,
                               const float* __restrict__ bias,
                               int M, int N, int K) {
    __shared__ float As[64][36];
    __shared__ float Ws[64][36];
    __shared__ float Cs[64][68];

    const int tid  = threadIdx.x;
    const int warp = tid >> 5;
    const int wm   = warp & 3;    // 0..3 -> 16-row slice
    const int wn   = warp >> 2;   // 0..1 -> 32-col slice
    const int row0A = blockIdx.y * 64;
    const int row0W = blockIdx.x * 64;

    wmma::fragment<wmma::accumulator, 16, 16, 8, float> acc[2];
    wmma::fill_fragment(acc[0], 0.f);
    wmma::fill_fragment(acc[1], 0.f);

    for (int k0 = 0; k0 < K; k0 += 32) {
#pragma unroll
        for (int r = 0; r < 2; r++) {
            int row = r * 32 + (tid >> 3);
            int c4  = (tid & 7) * 4;
            *(float4*)&As[row][c4] =
                *(const float4*)(A + (size_t)(row0A + row) * K + k0 + c4);
            *(float4*)&Ws[row][c4] =
                *(const float4*)(W + (size_t)(row0W + row) * K + k0 + c4);
        }
        __syncthreads();
#pragma unroll
        for (int kk = 0; kk < 32; kk += 8) {
            wmma::fragment<wmma::matrix_a, 16, 16, 8, wmma::precision::tf32, wmma::row_major> af;
            wmma::load_matrix_sync(af, &As[wm * 16][kk], 36);
#pragma unroll
            for (int i = 0; i < af.num_elements; i++) af.x[i] = wmma::__float_to_tf32(af.x[i]);
#pragma unroll
            for (int j = 0; j < 2; j++) {
                wmma::fragment<wmma::matrix_b, 16, 16, 8, wmma::precision::tf32, wmma::col_major> bf;
                wmma::load_matrix_sync(bf, &Ws[wn * 32 + j * 16][kk], 36);
#pragma unroll
                for (int i = 0; i < bf.num_elements; i++) bf.x[i] = wmma::__float_to_tf32(bf.x[i]);
                wmma::mma_sync(acc[j], af, bf, acc[j]);
            }
        }
        __syncthreads();
    }

    wmma::store_matrix_sync(&Cs[wm * 16][wn * 32],      acc[0], 68, wmma::mem_row_major);
    wmma::store_matrix_sync(&Cs[wm * 16][wn * 32 + 16], acc[1], 68, wmma::mem_row_major);
    __syncthreads();

    for (int idx = tid; idx < 64 * 64; idx += 256) {
        int r = idx >> 6, c = idx & 63;
        g_Xp[(size_t)(row0A + r) * N + row0W + c] = Cs[r][c] + bias[row0W + c];
    }
}

// ---------------- fused recurrent step ----------------
// One kernel per (layer, t). Grid = 64 CTAs, each owns 16 hidden units across
// all 4 gates (64 Wh rows) and all 64 batch rows. GEMM partial h@Wh^T (tf32 wmma)
// then LSTM cell epilogue in the same kernel.
__global__ void lstm_step_kernel(const float* __restrict__ Hprev, // [BSZ, HIDN]
                                 const float* __restrict__ Wh,    // [H4, HIDN]
                                 const float* __restrict__ Xp,    // [BSZ, H4] (row t)
                                 float* __restrict__ Hout,        // [BSZ, HIDN]
                                 int layer) {
    __shared__ float As[64][36];
    __shared__ float Ws[64][36];
    __shared__ float Gs[64][68];

    const int tid  = threadIdx.x;
    const int warp = tid >> 5;
    const int gate = warp >> 1;   // 0..3
    const int wm   = warp & 1;    // 0..1 -> 32 batch rows
    const int j0   = blockIdx.x * 16;

    wmma::fragment<wmma::accumulator, 16, 16, 8, float> acc[2];
    wmma::fill_fragment(acc[0], 0.f);
    wmma::fill_fragment(acc[1], 0.f);

    for (int k0 = 0; k0 < HIDN; k0 += 32) {
#pragma unroll
        for (int r = 0; r < 2; r++) {
            int row = r * 32 + (tid >> 3);
            int c4  = (tid & 7) * 4;
            *(float4*)&As[row][c4] =
                *(const float4*)(Hprev + (size_t)row * HIDN + k0 + c4);
            int g_ = row >> 4;            // gate of this smem row
            int u  = row & 15;            // unit within CTA slice
            int wr = g_ * HIDN + j0 + u;  // Wh global row
            *(float4*)&Ws[row][c4] =
                *(const float4*)(Wh + (size_t)wr * HIDN + k0 + c4);
        }
        __syncthreads();
#pragma unroll
        for (int kk = 0; kk < 32; kk += 8) {
            wmma::fragment<wmma::matrix_b, 16, 16, 8, wmma::precision::tf32, wmma::col_major> bf;
            wmma::load_matrix_sync(bf, &Ws[gate * 16][kk], 36);
#pragma unroll
            for (int i = 0; i < bf.num_elements; i++) bf.x[i] = wmma::__float_to_tf32(bf.x[i]);
#pragma unroll
            for (int f = 0; f < 2; f++) {
                wmma::fragment<wmma::matrix_a, 16, 16, 8, wmma::precision::tf32, wmma::row_major> af;
                wmma::load_matrix_sync(af, &As[wm * 32 + f * 16][kk], 36);
#pragma unroll
                for (int i = 0; i < af.num_elements; i++) af.x[i] = wmma::__float_to_tf32(af.x[i]);
                wmma::mma_sync(acc[f], af, bf, acc[f]);
            }
        }
        __syncthreads();
    }

    wmma::store_matrix_sync(&Gs[wm * 32][gate * 16],      acc[0], 68, wmma::mem_row_major);
    wmma::store_matrix_sync(&Gs[wm * 32 + 16][gate * 16], acc[1], 68, wmma::mem_row_major);
    __syncthreads();

    // LSTM cell epilogue: 64 batch x 16 units = 1024 elements, 4 per thread
    for (int idx = tid; idx < 64 * 16; idx += 256) {
        int b_ = idx >> 4;
        int u  = idx & 15;
        int j  = j0 + u;
        const float* xb = Xp + (size_t)b_ * H4;
        float gi = Gs[b_][u]           + xb[j];
        float gf = Gs[b_][16 + u]      + xb[HIDN + j];
        float go = Gs[b_][32 + u]      + xb[2 * HIDN + j];
        float gc = Gs[b_][48 + u]      + xb[3 * HIDN + j];
        float si = 1.f / (1.f + expf(-gi));
        float sf = 1.f / (1.f + expf(-gf));
        float so = 1.f / (1.f + expf(-go));
        float cold = g_c[layer][b_ * HIDN + j];
        float cn = sf * cold + si * tanhf(gc);
        float h  = so * tanhf(cn);
        g_c[layer][b_ * HIDN + j] = cn;
        Hout[(size_t)b_ * HIDN + j] = h;
    }
}

// ---------------- finalize: Hf / Cf ----------------
__global__ void finalize_kernel(const float* __restrict__ h0_last,
                                const float* __restrict__ h1_last,
                                float* __restrict__ Hf,
                                float* __restrict__ Cf) {
    int i = blockIdx.x * blockDim.x + threadIdx.x;
    if (i < BH) {
        Hf[i]      = h0_last[i];
        Hf[BH + i] = h1_last[i];
        Cf[i]      = g_c[0][i];
        Cf[BH + i] = g_c[1][i];
    }
}

// ---------------- launch ----------------
extern "C" void kernel_launch(void* const* d_in, const int* in_sizes, int n_in,
                              void* d_out, int out_size) {
    const float* X    = (const float*)d_in[0]; // [T, B, D]
    const float* Wx   = (const float*)d_in[1]; // [L, 4H, D]
    const float* Wh   = (const float*)d_in[2]; // [L, 4H, H]
    const float* bias = (const float*)d_in[3]; // [L, 4H]

    float* out     = (float*)d_out;
    float* outputs = out;                       // [T, B, H]
    float* Hf      = out + (size_t)TT * BH / 1; // after outputs
    Hf = out + (size_t)TT * BSZ * HIDN;
    float* Cf      = Hf + (size_t)NL * BH;

    float *Xp_p = nullptr, *H0_p = nullptr, *zero_p = nullptr;
    cudaGetSymbolAddress((void**)&Xp_p, g_Xp);
    cudaGetSymbolAddress((void**)&H0_p, g_H0);
    cudaGetSymbolAddress((void**)&zero_p, g_zero);

    init_kernel<<<(BH + 255) / 256, 256>>>();

    dim3 gg(H4 / 64, MTOT / 64);

    // Layer 0: precompute X @ Wx0^T + b0
    gemm_xp_kernel<<<gg, 256>>>(X, Wx, bias, MTOT, H4, DIN);
    // Layer 0 recurrence
    for (int t = 0; t < TT; t++) {
        const float* hp = t ? (H0_p + (size_t)(t - 1) * BH / 1) : zero_p;
        hp = t ? (H0_p + (size_t)(t - 1) * BSZ * HIDN) : zero_p;
        lstm_step_kernel<<<64, 256>>>(hp, Wh,
                                      Xp_p + (size_t)t * BSZ * H4,
                                      H0_p + (size_t)t * BSZ * HIDN, 0);
    }

    // Layer 1: precompute H0 @ Wx1^T + b1
    gemm_xp_kernel<<<gg, 256>>>(H0_p, Wx + (size_t)H4 * DIN, bias + H4, MTOT, H4, HIDN);
    // Layer 1 recurrence (writes directly to outputs region of d_out)
    for (int t = 0; t < TT; t++) {
        const float* hp = t ? (outputs + (size_t)(t - 1) * BSZ * HIDN) : zero_p;
        lstm_step_kernel<<<64, 256>>>(hp, Wh + (size_t)H4 * HIDN,
                                      Xp_p + (size_t)t * BSZ * H4,
                                      outputs + (size_t)t * BSZ * HIDN, 1);
    }

    finalize_kernel<<<(BH + 255) / 256, 256>>>(
        H0_p + (size_t)(TT - 1) * BSZ * HIDN,
        outputs + (size_t)(TT - 1) * BSZ * HIDN,
        Hf, Cf);
}